// round 15
// baseline (speedup 1.0000x reference)
#include <cuda_runtime.h>
#include <math.h>

#define HH 256
#define WW 256
#define CC 128
#define BIGF 1000000000.0f

// ---------------- device scratch ----------------
__device__ float g_cost[HH*WW*8];
__device__ float g_dist[2][HH*WW];
__device__ float g_geo [HH*WW];
__device__ float g_var [HH*WW];
__device__ float g_abs2[HH*WW];
__device__ float g_omega[HH*WW];
__device__ unsigned g_arrive;

__device__ __forceinline__ float softplusf(float x){
    return x > 30.0f ? x : log1pf(expf(x));
}

// packed f32x2 helpers (Blackwell SIMD2 fp32: add/mul/fma only)
__device__ __forceinline__ unsigned long long pk2(float x, float y){
    unsigned long long r;
    asm("mov.b64 %0, {%1, %2};" : "=l"(r) : "f"(x), "f"(y));
    return r;
}
__device__ __forceinline__ void fma2(unsigned long long &d, unsigned long long a,
                                     unsigned long long b){
    asm("fma.rn.f32x2 %0, %1, %2, %0;" : "+l"(d) : "l"(a), "l"(b));
}
__device__ __forceinline__ unsigned long long add2(unsigned long long a,
                                                   unsigned long long b){
    unsigned long long r;
    asm("add.rn.f32x2 %0, %1, %2;" : "=l"(r) : "l"(a), "l"(b));
    return r;
}
__device__ __forceinline__ float2 upk2(unsigned long long v){
    float2 r;
    asm("mov.b64 {%0, %1}, %2;" : "=f"(r.x), "=f"(r.y) : "l"(v));
    return r;
}

// ---------------- cost grid (R2-proven cost_k2) + dist BIG-init ----------------
// DIRS: 0:(-1,-1) 1:(-1,0) 2:(-1,1) 3:(0,-1) 4:(0,1) 5:(1,-1) 6:(1,0) 7:(1,1)
// cost[p][i] == cost[p+d_i][7-i]; compute i=4..7, mirror-write.
__global__ void cost_k(const float* __restrict__ f, float* __restrict__ out){
    __shared__ float sfeat[306*17];   // 17 rows x 18 cols cells, 16 ch, pad 17
    __shared__ float snorm[306];
    int tid = threadIdx.x;
    int tx = tid & 15, ty = tid >> 4;
    int bh = blockIdx.y*16, bw = blockIdx.x*16;
    int own = ty*18 + tx + 1;         // region: rows 0..16 (down halo), cols -1..16

    if (tid == 0 && blockIdx.x == 0 && blockIdx.y == 0) g_arrive = 0u;

    // halo cells (50): col -1 (17), col 16 (17), row 16 cols 0..15 (16)
    int hsidx = -1;
    if (tid < 17)      { hsidx = tid*18; }
    else if (tid < 34) { int r = tid-17; hsidx = r*18 + 17; }
    else if (tid < 50) { int c = tid-34; hsidx = 289 + c; }

    float dot4[4] = {0.f,0.f,0.f,0.f};
    float ownss = 0.0f, hss = 0.0f;
    const int nbo[4] = {1, 17, 18, 19};   // (0,1),(1,-1),(1,0),(1,1) in cell space

    for (int ck = 0; ck < 8; ck++){
        int c0 = ck*16;
        __syncthreads();
        for (int idx = tid; idx < 1224; idx += 256){
            int cell = idx >> 2, q = idx & 3;
            int r = cell / 18, cc = cell % 18;
            int gh = bh + r, gw = bw + cc - 1;
            float4 v = make_float4(0.f,0.f,0.f,0.f);
            if ((unsigned)gh < HH && (unsigned)gw < WW)
                v = *(const float4*)(f + (size_t)(gh*WW+gw)*CC + c0 + q*4);
            float* sp = sfeat + cell*17 + q*4;
            sp[0]=v.x; sp[1]=v.y; sp[2]=v.z; sp[3]=v.w;
        }
        __syncthreads();

        float a[16];
        #pragma unroll
        for (int ch=0; ch<16; ch++){
            a[ch] = sfeat[own*17 + ch];
            ownss = fmaf(a[ch], a[ch], ownss);
        }
        #pragma unroll
        for (int d=0; d<4; d++){
            const float* nb = sfeat + (own + nbo[d])*17;
            float s = 0.f;
            #pragma unroll
            for (int ch=0; ch<16; ch++) s = fmaf(a[ch], nb[ch], s);
            dot4[d] += s;
        }
        if (tid < 50){
            const float* hb = sfeat + hsidx*17;
            #pragma unroll
            for (int ch=0; ch<16; ch++) hss = fmaf(hb[ch], hb[ch], hss);
        }
    }
    __syncthreads();
    snorm[own] = ownss;
    if (tid < 50) snorm[hsidx] = hss;
    __syncthreads();

    int h = bh + ty, w = bw + tx;
    int px = h*WW + w;
    g_dist[0][px] = BIGF;             // BIG-init both dist buffers
    g_dist[1][px] = BIGF;
    float invp = 1.0f / fmaxf(sqrtf(ownss), 1e-12f);

    const int ddx[4] = {0,1,1,1};
    const int ddy[4] = {1,-1,0,1};
    #pragma unroll
    for (int d=0; d<4; d++){
        int i = 4 + d;
        int nh = h + ddx[d], nw = w + ddy[d];
        if ((unsigned)nh < HH && (unsigned)nw < WW){
            float nn = snorm[own + nbo[d]];
            float val = 1.0f - dot4[d] * invp / fmaxf(sqrtf(nn), 1e-12f);
            int npx = nh*WW + nw;
            g_cost[(size_t)px *8 + i]      = val;
            out   [(size_t)px *10 + 1 + i] = val;
            g_cost[(size_t)npx*8 + (7-i)]      = val;
            out   [(size_t)npx*10 + 1 + (7-i)] = val;
        } else {
            g_cost[(size_t)px*8 + i]      = BIGF;
            out   [(size_t)px*10 + 1 + i] = BIGF;
        }
    }
    const int udx[4] = {-1,-1,-1, 0};
    const int udy[4] = {-1, 0, 1,-1};
    #pragma unroll
    for (int j=0; j<4; j++){
        int nh = h + udx[j], nw = w + udy[j];
        if (!((unsigned)nh < HH && (unsigned)nw < WW)){
            g_cost[(size_t)px*8 + j]      = BIGF;
            out   [(size_t)px*10 + 1 + j] = BIGF;
        }
    }
}

// ---------------- heuristic + MLP (overlapped with dist on 2nd stream) ---------
__global__ void heur_k(const float* __restrict__ f,
                       const float* __restrict__ w1, const float* __restrict__ b1,
                       const float* __restrict__ w2, const float* __restrict__ b2,
                       const int* __restrict__ endn){
    extern __shared__ float dyn[];
    float* sw     = dyn;                       // 4096 floats (W1)
    float* sbuf   = dyn + 4096;                // 2 x 5508 floats
    float* sendlf = dyn + 4096 + 11016;        // 64

    int tid = threadIdx.x;
    int tx = tid & 15, ty = tid >> 4;
    int bh = blockIdx.y*16, bw = blockIdx.x*16;
    int base = (ty+1)*18 + (tx+1);

    for (int i = tid; i < 1024; i += 256)
        *(float4*)(sw + i*4) = *(const float4*)(w1 + i*4);
    if (tid < 16){
        int e = endn[0]*WW + endn[1];
        *(float4*)(sendlf + tid*4) = *(const float4*)(f + (size_t)e*CC + tid*4);
    }

    for (int idx = tid; idx < 11016; idx += 256) sbuf[idx] = 0.0f;
    __syncthreads();

    float geo = 0.0f, var = 0.0f, ab2 = 0.0f;

    unsigned long long macc[16];
    #pragma unroll
    for (int j=0;j<16;j++) macc[j] = pk2(b1[2*j], b1[2*j+1]);

    auto issue_chunk = [&](int ck, int bsel){
        int c0 = ck*16;
        float* dst = sbuf + bsel*5508;
        for (int idx = tid; idx < 5184; idx += 256){
            int cell = idx >> 4, ch = idx & 15;
            int r = cell / 18, col = cell - r*18;
            int gh = bh + r - 1, gw = bw + col - 1;
            if ((unsigned)gh < HH && (unsigned)gw < WW){
                unsigned sa = (unsigned)__cvta_generic_to_shared(dst + cell*17 + ch);
                asm volatile("cp.async.ca.shared.global [%0], [%1], 4;\n"
                             :: "r"(sa), "l"(f + (size_t)(gh*WW+gw)*CC + c0 + ch));
            }
        }
        asm volatile("cp.async.commit_group;\n");
    };

    issue_chunk(0, 0);

    for (int ck = 0; ck < 8; ck++){
        asm volatile("cp.async.wait_group 0;\n" ::: "memory");
        __syncthreads();
        if (ck < 7) issue_chunk(ck+1, (ck+1)&1);

        const float* sb = sbuf + (ck&1)*5508;
        int c0 = ck*16;

        #pragma unroll
        for (int ch = 0; ch < 16; ch++){
            float v00 = sb[(base-19)*17+ch], v01 = sb[(base-18)*17+ch], v02 = sb[(base-17)*17+ch];
            float v10 = sb[(base- 1)*17+ch], v11 = sb[(base   )*17+ch], v12 = sb[(base+ 1)*17+ch];
            float v20 = sb[(base+17)*17+ch], v21 = sb[(base+18)*17+ch], v22 = sb[(base+19)*17+ch];
            float gx = (v02 - v00) + 2.0f*(v12 - v10) + (v22 - v20);
            float gy = (v20 - v00) + 2.0f*(v21 - v01) + (v22 - v02);
            geo += sqrtf(gx*gx + gy*gy);
            {
                unsigned long long f2 = pk2(v11, v11);
                const ulonglong2* wr = (const ulonglong2*)(sw + (c0 + ch)*32);
                #pragma unroll
                for (int q = 0; q < 8; q++){
                    ulonglong2 wv = wr[q];
                    fma2(macc[2*q  ], f2, wv.x);
                    fma2(macc[2*q+1], f2, wv.y);
                }
            }
            int c = c0 + ch;
            if (c >= 64){
                float xs = v00+v01+v02+v10+v11+v12+v20+v21+v22;
                float x2 = v00*v00+v01*v01+v02*v02+v10*v10+v11*v11+v12*v12+v20*v20+v21*v21+v22*v22;
                float m1 = xs * (1.0f/9.0f);
                var += x2 * (1.0f/9.0f) - m1*m1;
            } else {
                float d = v11 - sendlf[c];
                ab2 += d*d;
            }
        }
    }

    int px = (bh+ty)*WW + (bw+tx);
    g_geo [px] = geo * (1.0f/128.0f);
    g_var [px] = var;
    g_abs2[px] = ab2;

    {
        float z = b2[0];
        #pragma unroll
        for (int j=0;j<16;j++){
            float2 u = upk2(macc[j]);
            z = fmaf(fmaxf(u.x, 0.0f), w2[2*j],   z);
            z = fmaf(fmaxf(u.y, 0.0f), w2[2*j+1], z);
        }
        g_omega[px] = 1.0f / (1.0f + expf(-z));
    }
}

// ---------------- persistent relaxation: 16 phases x K=16, 128 blocks ----------
// (R14 structure; final phase stores to g_dist[0] like all others)
__global__ void __launch_bounds__(768,1) dist_relax_persist(const int* __restrict__ startn){
    __shared__ __align__(16) float sd[2][50][66];
    int tid = threadIdx.x;
    int tx2 = tid & 31, ty2 = tid >> 5;
    int rr = 2*ty2, cc = 2*tx2;
    int bh = blockIdx.y*16 - 16, bw = blockIdx.x*32 - 16;
    const unsigned NBLK = 128u;

    int sh = startn[0], sw_ = startn[1];
    int d0;
    {
        int rlo = max(bh, 0),  rhi = min(bh+47, HH-1);
        int clo = max(bw, 0),  chi = min(bw+63, WW-1);
        int dr = max(max(rlo - sh, sh - rhi), 0);
        int dc = max(max(clo - sw_, sw_ - chi), 0);
        d0 = max(dr, dc);
    }

    for (int idx = tid; idx < 2*50*66; idx += 768){
        int l = idx / (50*66);
        int rem = idx % (50*66);
        int r = rem / 66, c = rem % 66;
        if (r == 0 || r == 49 || c == 0 || c == 65)
            sd[l][r][c] = BIGF;
    }

    unsigned long long cst2t[8], cst2b[8];
    {
        float cl[2][2][8];
        #pragma unroll
        for (int a=0;a<2;a++)
        #pragma unroll
        for (int b=0;b<2;b++){
            int gh = bh + rr + a, gw = bw + cc + b;
            if ((unsigned)gh < HH && (unsigned)gw < WW){
                const float4* cp = (const float4*)(g_cost + (size_t)(gh*WW+gw)*8);
                float4 u = __ldg(cp), w = __ldg(cp+1);
                cl[a][b][0]=u.x; cl[a][b][1]=u.y; cl[a][b][2]=u.z; cl[a][b][3]=u.w;
                cl[a][b][4]=w.x; cl[a][b][5]=w.y; cl[a][b][6]=w.z; cl[a][b][7]=w.w;
            } else {
                #pragma unroll
                for (int i=0;i<8;i++) cl[a][b][i] = BIGF;
            }
        }
        #pragma unroll
        for (int i=0;i<8;i++){
            cst2t[i] = pk2(cl[0][0][i], cl[0][1][i]);
            cst2b[i] = pk2(cl[1][0][i], cl[1][1][i]);
        }
    }

    for (int idx = tid; idx < 3072; idx += 768){
        int r = idx >> 6, c = idx & 63;
        int gh = bh + r, gw = bw + c;
        sd[0][r+1][c+1] = (gh == sh && gw == sw_) ? 0.0f : BIGF;
    }

    bool is_store = (ty2 >= 8 && ty2 < 16 && tx2 >= 8 && tx2 < 24);
    int gh_s = bh + rr, gw_s = bw + cc;

    #pragma unroll 1
    for (int p = 0; p < 16; p++){
        float* __restrict__ dst = g_dist[(p+1) & 1];
        bool skip = (d0 > 16*(p+1));

        if (!skip){
            if (p > 0){
                const float* __restrict__ src = g_dist[p & 1];
                for (int idx = tid; idx < 2560; idx += 768){
                    int r, c;
                    if (idx < 1024)      { r = idx >> 6;               c = idx & 63; }
                    else if (idx < 2048) { r = 32 + ((idx-1024) >> 6); c = idx & 63; }
                    else if (idx < 2304) { int t = idx-2048; r = 16 + (t >> 4); c = t & 15; }
                    else                 { int t = idx-2304; r = 16 + (t >> 4); c = 48 + (t & 15); }
                    int gh = bh + r, gw = bw + c;
                    float v = BIGF;
                    if ((unsigned)gh < HH && (unsigned)gw < WW)
                        v = __ldcg(src + gh*WW + gw);
                    sd[0][r+1][c+1] = v;
                }
            }
            __syncthreads();

            #pragma unroll
            for (int it = 0; it < 16; it++){
                const int cur = it & 1;
                bool colok = (cc+1 >= 1+it) && (cc <= 62-it);
                bool act_t = colok && (rr   >= 1+it) && (rr   <= 46-it);
                bool act_b = colok && (rr+1 >= 1+it) && (rr+1 <= 46-it);

                if (act_t | act_b){
                    unsigned long long B0 = *(const unsigned long long*)&sd[cur][rr+1][cc];
                    unsigned long long B1 = *(const unsigned long long*)&sd[cur][rr+1][cc+2];
                    unsigned long long C0 = *(const unsigned long long*)&sd[cur][rr+2][cc];
                    unsigned long long C1 = *(const unsigned long long*)&sd[cur][rr+2][cc+2];
                    float2 fB0 = upk2(B0), fB1 = upk2(B1);
                    float2 fC0 = upk2(C0), fC1 = upk2(C1);
                    unsigned long long mixB = pk2(fB0.y, fB1.x);
                    unsigned long long mixC = pk2(fC0.y, fC1.x);

                    if (act_t){
                        unsigned long long A0 = *(const unsigned long long*)&sd[cur][rr][cc];
                        unsigned long long A1 = *(const unsigned long long*)&sd[cur][rr][cc+2];
                        float2 fA0 = upk2(A0), fA1 = upk2(A1);
                        unsigned long long mixA = pk2(fA0.y, fA1.x);

                        unsigned long long s0 = add2(A0,   cst2t[0]);
                        unsigned long long s1 = add2(mixA, cst2t[1]);
                        unsigned long long s2 = add2(A1,   cst2t[2]);
                        unsigned long long s3 = add2(B0,   cst2t[3]);
                        unsigned long long s4 = add2(B1,   cst2t[4]);
                        unsigned long long s5 = add2(C0,   cst2t[5]);
                        unsigned long long s6 = add2(mixC, cst2t[6]);
                        unsigned long long s7 = add2(C1,   cst2t[7]);
                        float2 u0=upk2(s0),u1=upk2(s1),u2=upk2(s2),u3=upk2(s3);
                        float2 u4=upk2(s4),u5=upk2(s5),u6=upk2(s6),u7=upk2(s7);
                        float v0 = fminf(fB0.y,
                                   fminf(fminf(fminf(u0.x,u1.x), fminf(u2.x,u3.x)),
                                         fminf(fminf(u4.x,u5.x), fminf(u6.x,u7.x))));
                        float v1 = fminf(fB1.x,
                                   fminf(fminf(fminf(u0.y,u1.y), fminf(u2.y,u3.y)),
                                         fminf(fminf(u4.y,u5.y), fminf(u6.y,u7.y))));
                        sd[cur^1][rr+1][cc+1] = v0;
                        sd[cur^1][rr+1][cc+2] = v1;
                    }
                    if (act_b){
                        unsigned long long D0 = *(const unsigned long long*)&sd[cur][rr+3][cc];
                        unsigned long long D1 = *(const unsigned long long*)&sd[cur][rr+3][cc+2];
                        float2 fD0 = upk2(D0), fD1 = upk2(D1);
                        unsigned long long mixD = pk2(fD0.y, fD1.x);

                        unsigned long long s0 = add2(B0,   cst2b[0]);
                        unsigned long long s1 = add2(mixB, cst2b[1]);
                        unsigned long long s2 = add2(B1,   cst2b[2]);
                        unsigned long long s3 = add2(C0,   cst2b[3]);
                        unsigned long long s4 = add2(C1,   cst2b[4]);
                        unsigned long long s5 = add2(D0,   cst2b[5]);
                        unsigned long long s6 = add2(mixD, cst2b[6]);
                        unsigned long long s7 = add2(D1,   cst2b[7]);
                        float2 u0=upk2(s0),u1=upk2(s1),u2=upk2(s2),u3=upk2(s3);
                        float2 u4=upk2(s4),u5=upk2(s5),u6=upk2(s6),u7=upk2(s7);
                        float v0 = fminf(fC0.y,
                                   fminf(fminf(fminf(u0.x,u1.x), fminf(u2.x,u3.x)),
                                         fminf(fminf(u4.x,u5.x), fminf(u6.x,u7.x))));
                        float v1 = fminf(fC1.x,
                                   fminf(fminf(fminf(u0.y,u1.y), fminf(u2.y,u3.y)),
                                         fminf(fminf(u4.y,u5.y), fminf(u6.y,u7.y))));
                        sd[cur^1][rr+2][cc+1] = v0;
                        sd[cur^1][rr+2][cc+2] = v1;
                    }
                }
                __syncthreads();
            }

            if (is_store){
                __stcg(dst + (gh_s  )*WW + gw_s,     sd[0][rr+1][cc+1]);
                __stcg(dst + (gh_s  )*WW + gw_s + 1, sd[0][rr+1][cc+2]);
                __stcg(dst + (gh_s+1)*WW + gw_s,     sd[0][rr+2][cc+1]);
                __stcg(dst + (gh_s+1)*WW + gw_s + 1, sd[0][rr+2][cc+2]);
            }
            if (p < 15) __threadfence();
        }

        if (p < 15){
            __syncthreads();
            if (tid == 0){
                atomicAdd(&g_arrive, 1u);
                unsigned target = NBLK * (unsigned)(p + 1);
                while (*((volatile unsigned*)&g_arrive) < target) __nanosleep(64);
            }
            __syncthreads();
        }
    }
}

// ---------------- final pack: heuristic + dist channels ----------------
__global__ void pack_k(float* __restrict__ out, const int* __restrict__ endn,
                       const float* __restrict__ dl, const float* __restrict__ gm,
                       const float* __restrict__ bt){
    int px = blockIdx.x*256 + threadIdx.x;
    int e = endn[0]*WW + endn[1];
    float om = g_omega[px];
    float varEnd = g_var[e];
    float q0 = softplusf(*dl), q1 = softplusf(*gm), q2 = softplusf(*bt);
    float hval = q0*g_geo[px]
               + om*q1*(varEnd - g_var[px])
               + (1.0f - om)*q2*sqrtf(g_abs2[px]);
    out[(size_t)px*10 + 0] = fmaxf(hval, 0.0f);
    out[(size_t)px*10 + 9] = fminf(g_dist[0][px], BIGF);
}

// ---------------- launch: fork heur_k onto a second capture stream -------------
extern "C" void kernel_launch(void* const* d_in, const int* in_sizes, int n_in,
                              void* d_out, int out_size){
    const float* f = (const float*)d_in[0];
    float* out = (float*)d_out;

    static cudaStream_t s2 = nullptr;
    static cudaEvent_t ev1, ev2;
    if (!s2){
        cudaStreamCreateWithFlags(&s2, cudaStreamNonBlocking);
        cudaEventCreateWithFlags(&ev1, cudaEventDisableTiming);
        cudaEventCreateWithFlags(&ev2, cudaEventDisableTiming);
        cudaFuncSetAttribute(heur_k, cudaFuncAttributeMaxDynamicSharedMemorySize, 60704);
    }

    // fork: heur_k runs concurrently with cost_k + dist on stream s2
    cudaEventRecord(ev1, 0);
    cudaStreamWaitEvent(s2, ev1, 0);
    heur_k<<<dim3(16,16), 256, 60704, s2>>>(f, (const float*)d_in[4], (const float*)d_in[5],
                                            (const float*)d_in[6], (const float*)d_in[7],
                                            (const int*)d_in[9]);
    cudaEventRecord(ev2, s2);

    cost_k<<<dim3(16,16), 256>>>(f, out);
    dist_relax_persist<<<dim3(8,16), 768>>>((const int*)d_in[8]);

    // join: pack needs both dist (main stream) and heur (s2)
    cudaStreamWaitEvent(0, ev2, 0);
    pack_k<<<256, 256>>>(out, (const int*)d_in[9], (const float*)d_in[1],
                         (const float*)d_in[2], (const float*)d_in[3]);
}

// round 16
// speedup vs baseline: 1.2302x; 1.2302x over previous
#include <cuda_runtime.h>
#include <math.h>

#define HH 256
#define WW 256
#define CC 128
#define BIGF 1000000000.0f

// ---------------- device scratch ----------------
__device__ float g_cost[HH*WW*8];
__device__ float g_dist[2][HH*WW];
__device__ float g_geo [HH*WW];
__device__ float g_var [HH*WW];
__device__ float g_abs2[HH*WW];
__device__ float g_omega[HH*WW];
__device__ unsigned g_arrive;

__device__ __forceinline__ float softplusf(float x){
    return x > 30.0f ? x : log1pf(expf(x));
}

// packed f32x2 helpers (Blackwell SIMD2 fp32: add/mul/fma only)
__device__ __forceinline__ unsigned long long pk2(float x, float y){
    unsigned long long r;
    asm("mov.b64 %0, {%1, %2};" : "=l"(r) : "f"(x), "f"(y));
    return r;
}
__device__ __forceinline__ void fma2(unsigned long long &d, unsigned long long a,
                                     unsigned long long b){
    asm("fma.rn.f32x2 %0, %1, %2, %0;" : "+l"(d) : "l"(a), "l"(b));
}
__device__ __forceinline__ unsigned long long add2(unsigned long long a,
                                                   unsigned long long b){
    unsigned long long r;
    asm("add.rn.f32x2 %0, %1, %2;" : "=l"(r) : "l"(a), "l"(b));
    return r;
}
__device__ __forceinline__ unsigned long long mul2(unsigned long long a,
                                                   unsigned long long b){
    unsigned long long r;
    asm("mul.rn.f32x2 %0, %1, %2;" : "=l"(r) : "l"(a), "l"(b));
    return r;
}
__device__ __forceinline__ float2 upk2(unsigned long long v){
    float2 r;
    asm("mov.b64 {%0, %1}, %2;" : "=f"(r.x), "=f"(r.y) : "l"(v));
    return r;
}

// ---------------- fused heuristic + cost + MLP + dist BIG-init ----------------
// Channel-PAIR processing: SMEM pad 18, LDS.64 loads, packed f32x2 stencil math.
// DIRS: 0:(-1,-1) 1:(-1,0) 2:(-1,1) 3:(0,-1) 4:(0,1) 5:(1,-1) 6:(1,0) 7:(1,1)
// cost[p][i] == cost[p+d_i][7-i]; compute i=4..7, mirror-write.
__global__ void hc_k(const float* __restrict__ f, float* __restrict__ out,
                     const float* __restrict__ w1, const float* __restrict__ b1,
                     const float* __restrict__ w2, const float* __restrict__ b2,
                     const int* __restrict__ endn){
    extern __shared__ float dyn[];
    float* sw     = dyn;                       // 4096 floats (W1)
    float* sbuf   = dyn + 4096;                // 2 x (324 cells x 18) = 11664
    float* snorm  = dyn + 4096 + 11664;        // 324
    float* sendlf = snorm + 324;               // 64  (offset 16084, 16B aligned)

    int tid = threadIdx.x;
    int tx = tid & 15, ty = tid >> 4;
    int bh = blockIdx.y*16, bw = blockIdx.x*16;
    int base = (ty+1)*18 + (tx+1);             // cell index

    if (tid == 0 && blockIdx.x == 0 && blockIdx.y == 0) g_arrive = 0u;

    for (int i = tid; i < 1024; i += 256)
        *(float4*)(sw + i*4) = *(const float4*)(w1 + i*4);
    if (tid < 16){
        int e = endn[0]*WW + endn[1];
        *(float4*)(sendlf + tid*4) = *(const float4*)(f + (size_t)e*CC + tid*4);
    }

    for (int idx = tid; idx < 11664; idx += 256) sbuf[idx] = 0.0f;
    __syncthreads();

    int eidx = -1;
    if (tid < 16)      eidx = (tid+2)*18;            // col 0, rows 2..17
    else if (tid < 33) eidx = (tid-15)*18 + 17;      // col 17, rows 1..17
    else if (tid < 49) eidx = 17*18 + (tid-32);      // row 17, cols 1..16

    const unsigned long long PKm1 = pk2(-1.0f,-1.0f);
    const unsigned long long PKp2 = pk2( 2.0f, 2.0f);
    const unsigned long long PKm2 = pk2(-2.0f,-2.0f);
    const unsigned long long PK0  = pk2( 0.0f, 0.0f);

    float geo = 0.0f, var = 0.0f, ab2 = 0.0f;
    unsigned long long own2 = PK0, ep2 = PK0;
    unsigned long long dotp0 = PK0, dotp1 = PK0, dotp2 = PK0, dotp3 = PK0;

    unsigned long long macc[16];
    #pragma unroll
    for (int j=0;j<16;j++) macc[j] = pk2(b1[2*j], b1[2*j+1]);

    auto issue_chunk = [&](int ck, int bsel){
        int c0 = ck*16;
        float* dst = sbuf + bsel*5832;
        for (int idx = tid; idx < 5184; idx += 256){
            int cell = idx >> 4, ch = idx & 15;
            int r = cell / 18, col = cell - r*18;
            int gh = bh + r - 1, gw = bw + col - 1;
            if ((unsigned)gh < HH && (unsigned)gw < WW){
                unsigned sa = (unsigned)__cvta_generic_to_shared(dst + cell*18 + ch);
                asm volatile("cp.async.ca.shared.global [%0], [%1], 4;\n"
                             :: "r"(sa), "l"(f + (size_t)(gh*WW+gw)*CC + c0 + ch));
            }
        }
        asm volatile("cp.async.commit_group;\n");
    };

    issue_chunk(0, 0);

    for (int ck = 0; ck < 8; ck++){
        asm volatile("cp.async.wait_group 0;\n" ::: "memory");
        __syncthreads();
        if (ck < 7) issue_chunk(ck+1, (ck+1)&1);

        const float* sb = sbuf + (ck&1)*5832;
        int c0 = ck*16;

        #pragma unroll
        for (int pr = 0; pr < 8; pr++){
            int chp = 2*pr;
            const float* cb = sb + chp;
            unsigned long long v00 = *(const unsigned long long*)&cb[(base-19)*18];
            unsigned long long v01 = *(const unsigned long long*)&cb[(base-18)*18];
            unsigned long long v02 = *(const unsigned long long*)&cb[(base-17)*18];
            unsigned long long v10 = *(const unsigned long long*)&cb[(base- 1)*18];
            unsigned long long v11 = *(const unsigned long long*)&cb[(base   )*18];
            unsigned long long v12 = *(const unsigned long long*)&cb[(base+ 1)*18];
            unsigned long long v20 = *(const unsigned long long*)&cb[(base+17)*18];
            unsigned long long v21 = *(const unsigned long long*)&cb[(base+18)*18];
            unsigned long long v22 = *(const unsigned long long*)&cb[(base+19)*18];

            // packed Sobel
            unsigned long long gx = v02;
            fma2(gx, v00, PKm1); fma2(gx, v12, PKp2); fma2(gx, v10, PKm2);
            gx = add2(gx, v22);  fma2(gx, v20, PKm1);
            unsigned long long gy = v20;
            fma2(gy, v00, PKm1); fma2(gy, v21, PKp2); fma2(gy, v01, PKm2);
            gy = add2(gy, v22);  fma2(gy, v02, PKm1);
            float2 fgx = upk2(gx), fgy = upk2(gy);
            geo += sqrtf(fgx.x*fgx.x + fgy.x*fgy.x);
            geo += sqrtf(fgx.y*fgx.y + fgy.y*fgy.y);

            // packed norm + cost dots
            fma2(own2,  v11, v11);
            fma2(dotp0, v11, v12);   // (0, 1)
            fma2(dotp1, v11, v20);   // (1,-1)
            fma2(dotp2, v11, v21);   // (1, 0)
            fma2(dotp3, v11, v22);   // (1, 1)

            // MLP layer-1 (broadcast each channel of the pair)
            float2 f11 = upk2(v11);
            {
                unsigned long long fa = pk2(f11.x, f11.x);
                unsigned long long fb = pk2(f11.y, f11.y);
                const ulonglong2* wrA = (const ulonglong2*)(sw + (c0+chp  )*32);
                const ulonglong2* wrB = (const ulonglong2*)(sw + (c0+chp+1)*32);
                #pragma unroll
                for (int q = 0; q < 8; q++){
                    ulonglong2 wv = wrA[q];
                    fma2(macc[2*q  ], fa, wv.x);
                    fma2(macc[2*q+1], fa, wv.y);
                }
                #pragma unroll
                for (int q = 0; q < 8; q++){
                    ulonglong2 wv = wrB[q];
                    fma2(macc[2*q  ], fb, wv.x);
                    fma2(macc[2*q+1], fb, wv.y);
                }
            }

            int c = c0 + chp;
            if (c >= 64){
                unsigned long long xs = add2(v00, v01);
                xs = add2(xs, v02); xs = add2(xs, v10); xs = add2(xs, v11);
                xs = add2(xs, v12); xs = add2(xs, v20); xs = add2(xs, v21);
                xs = add2(xs, v22);
                unsigned long long x2 = PK0;
                fma2(x2, v00, v00); fma2(x2, v01, v01); fma2(x2, v02, v02);
                fma2(x2, v10, v10); fma2(x2, v11, v11); fma2(x2, v12, v12);
                fma2(x2, v20, v20); fma2(x2, v21, v21); fma2(x2, v22, v22);
                float2 fxs = upk2(xs), fx2 = upk2(x2);
                float m1a = fxs.x * (1.0f/9.0f);
                float m1b = fxs.y * (1.0f/9.0f);
                var += fx2.x * (1.0f/9.0f) - m1a*m1a;
                var += fx2.y * (1.0f/9.0f) - m1b*m1b;
            } else {
                float da = f11.x - sendlf[c];
                float db = f11.y - sendlf[c+1];
                ab2 = fmaf(da, da, ab2);
                ab2 = fmaf(db, db, ab2);
            }
        }
        if (tid < 49){
            const float* eb = sb + eidx*18;
            #pragma unroll
            for (int i2 = 0; i2 < 8; i2++){
                unsigned long long e = *(const unsigned long long*)&eb[2*i2];
                fma2(ep2, e, e);
            }
        }
    }

    float ownss;
    float dot4[4];
    {
        float2 t = upk2(own2); ownss = t.x + t.y;
        t = upk2(dotp0); dot4[0] = t.x + t.y;
        t = upk2(dotp1); dot4[1] = t.x + t.y;
        t = upk2(dotp2); dot4[2] = t.x + t.y;
        t = upk2(dotp3); dot4[3] = t.x + t.y;
    }

    int px = (bh+ty)*WW + (bw+tx);
    g_geo [px] = geo * (1.0f/128.0f);
    g_var [px] = var;
    g_abs2[px] = ab2;
    g_dist[0][px] = BIGF;
    g_dist[1][px] = BIGF;

    {
        float z = b2[0];
        #pragma unroll
        for (int j=0;j<16;j++){
            float2 u = upk2(macc[j]);
            z = fmaf(fmaxf(u.x, 0.0f), w2[2*j],   z);
            z = fmaf(fmaxf(u.y, 0.0f), w2[2*j+1], z);
        }
        g_omega[px] = 1.0f / (1.0f + expf(-z));
    }

    __syncthreads();
    snorm[base] = ownss;
    if (tid < 49){
        float2 t = upk2(ep2);
        snorm[eidx] = t.x + t.y;
    }
    __syncthreads();

    int h = bh + ty, w = bw + tx;
    float invp = 1.0f / fmaxf(sqrtf(ownss), 1e-12f);
    const int nbo[4] = {1, 17, 18, 19};
    const int ddx[4] = {0,1,1,1};
    const int ddy[4] = {1,-1,0,1};
    #pragma unroll
    for (int d=0; d<4; d++){
        int i = 4 + d;
        int nh = h + ddx[d], nw = w + ddy[d];
        if ((unsigned)nh < HH && (unsigned)nw < WW){
            float nn = snorm[base + nbo[d]];
            float val = 1.0f - dot4[d] * invp / fmaxf(sqrtf(nn), 1e-12f);
            int npx = nh*WW + nw;
            g_cost[(size_t)px *8 + i]          = val;
            out   [(size_t)px *10 + 1 + i]     = val;
            g_cost[(size_t)npx*8 + (7-i)]      = val;
            out   [(size_t)npx*10 + 1 + (7-i)] = val;
        } else {
            g_cost[(size_t)px*8 + i]      = BIGF;
            out   [(size_t)px*10 + 1 + i] = BIGF;
        }
    }
    const int udx[4] = {-1,-1,-1, 0};
    const int udy[4] = {-1, 0, 1,-1};
    #pragma unroll
    for (int j=0; j<4; j++){
        int nh = h + udx[j], nw = w + udy[j];
        if (!((unsigned)nh < HH && (unsigned)nw < WW)){
            g_cost[(size_t)px*8 + j]      = BIGF;
            out   [(size_t)px*10 + 1 + j] = BIGF;
        }
    }
}

// ---------------- persistent relaxation: 16 phases x K=16, 128 blocks ----------
// (R14 verbatim — proven)
__global__ void __launch_bounds__(768,1) dist_relax_persist(const int* __restrict__ startn,
                                                            const int* __restrict__ endn,
                                                            const float* __restrict__ dl,
                                                            const float* __restrict__ gm,
                                                            const float* __restrict__ bt,
                                                            float* __restrict__ out){
    __shared__ __align__(16) float sd[2][50][66];
    int tid = threadIdx.x;
    int tx2 = tid & 31, ty2 = tid >> 5;
    int rr = 2*ty2, cc = 2*tx2;
    int bh = blockIdx.y*16 - 16, bw = blockIdx.x*32 - 16;
    const unsigned NBLK = 128u;

    int sh = startn[0], sw_ = startn[1];
    int d0;
    {
        int rlo = max(bh, 0),  rhi = min(bh+47, HH-1);
        int clo = max(bw, 0),  chi = min(bw+63, WW-1);
        int dr = max(max(rlo - sh, sh - rhi), 0);
        int dc = max(max(clo - sw_, sw_ - chi), 0);
        d0 = max(dr, dc);
    }

    for (int idx = tid; idx < 2*50*66; idx += 768){
        int l = idx / (50*66);
        int rem = idx % (50*66);
        int r = rem / 66, c = rem % 66;
        if (r == 0 || r == 49 || c == 0 || c == 65)
            sd[l][r][c] = BIGF;
    }

    unsigned long long cst2t[8], cst2b[8];
    {
        float cl[2][2][8];
        #pragma unroll
        for (int a=0;a<2;a++)
        #pragma unroll
        for (int b=0;b<2;b++){
            int gh = bh + rr + a, gw = bw + cc + b;
            if ((unsigned)gh < HH && (unsigned)gw < WW){
                const float4* cp = (const float4*)(g_cost + (size_t)(gh*WW+gw)*8);
                float4 u = __ldg(cp), w = __ldg(cp+1);
                cl[a][b][0]=u.x; cl[a][b][1]=u.y; cl[a][b][2]=u.z; cl[a][b][3]=u.w;
                cl[a][b][4]=w.x; cl[a][b][5]=w.y; cl[a][b][6]=w.z; cl[a][b][7]=w.w;
            } else {
                #pragma unroll
                for (int i=0;i<8;i++) cl[a][b][i] = BIGF;
            }
        }
        #pragma unroll
        for (int i=0;i<8;i++){
            cst2t[i] = pk2(cl[0][0][i], cl[0][1][i]);
            cst2b[i] = pk2(cl[1][0][i], cl[1][1][i]);
        }
    }

    for (int idx = tid; idx < 3072; idx += 768){
        int r = idx >> 6, c = idx & 63;
        int gh = bh + r, gw = bw + c;
        sd[0][r+1][c+1] = (gh == sh && gw == sw_) ? 0.0f : BIGF;
    }

    bool is_store = (ty2 >= 8 && ty2 < 16 && tx2 >= 8 && tx2 < 24);
    int gh_s = bh + rr, gw_s = bw + cc;

    #pragma unroll 1
    for (int p = 0; p < 16; p++){
        float* __restrict__ dst = g_dist[(p+1) & 1];
        bool skip = (d0 > 16*(p+1));

        if (!skip){
            if (p > 0){
                const float* __restrict__ src = g_dist[p & 1];
                for (int idx = tid; idx < 2560; idx += 768){
                    int r, c;
                    if (idx < 1024)      { r = idx >> 6;               c = idx & 63; }
                    else if (idx < 2048) { r = 32 + ((idx-1024) >> 6); c = idx & 63; }
                    else if (idx < 2304) { int t = idx-2048; r = 16 + (t >> 4); c = t & 15; }
                    else                 { int t = idx-2304; r = 16 + (t >> 4); c = 48 + (t & 15); }
                    int gh = bh + r, gw = bw + c;
                    float v = BIGF;
                    if ((unsigned)gh < HH && (unsigned)gw < WW)
                        v = __ldcg(src + gh*WW + gw);
                    sd[0][r+1][c+1] = v;
                }
            }
            __syncthreads();

            #pragma unroll
            for (int it = 0; it < 16; it++){
                const int cur = it & 1;
                bool colok = (cc+1 >= 1+it) && (cc <= 62-it);
                bool act_t = colok && (rr   >= 1+it) && (rr   <= 46-it);
                bool act_b = colok && (rr+1 >= 1+it) && (rr+1 <= 46-it);

                if (act_t | act_b){
                    unsigned long long B0 = *(const unsigned long long*)&sd[cur][rr+1][cc];
                    unsigned long long B1 = *(const unsigned long long*)&sd[cur][rr+1][cc+2];
                    unsigned long long C0 = *(const unsigned long long*)&sd[cur][rr+2][cc];
                    unsigned long long C1 = *(const unsigned long long*)&sd[cur][rr+2][cc+2];
                    float2 fB0 = upk2(B0), fB1 = upk2(B1);
                    float2 fC0 = upk2(C0), fC1 = upk2(C1);
                    unsigned long long mixB = pk2(fB0.y, fB1.x);
                    unsigned long long mixC = pk2(fC0.y, fC1.x);

                    if (act_t){
                        unsigned long long A0 = *(const unsigned long long*)&sd[cur][rr][cc];
                        unsigned long long A1 = *(const unsigned long long*)&sd[cur][rr][cc+2];
                        float2 fA0 = upk2(A0), fA1 = upk2(A1);
                        unsigned long long mixA = pk2(fA0.y, fA1.x);

                        unsigned long long s0 = add2(A0,   cst2t[0]);
                        unsigned long long s1 = add2(mixA, cst2t[1]);
                        unsigned long long s2 = add2(A1,   cst2t[2]);
                        unsigned long long s3 = add2(B0,   cst2t[3]);
                        unsigned long long s4 = add2(B1,   cst2t[4]);
                        unsigned long long s5 = add2(C0,   cst2t[5]);
                        unsigned long long s6 = add2(mixC, cst2t[6]);
                        unsigned long long s7 = add2(C1,   cst2t[7]);
                        float2 u0=upk2(s0),u1=upk2(s1),u2=upk2(s2),u3=upk2(s3);
                        float2 u4=upk2(s4),u5=upk2(s5),u6=upk2(s6),u7=upk2(s7);
                        float v0 = fminf(fB0.y,
                                   fminf(fminf(fminf(u0.x,u1.x), fminf(u2.x,u3.x)),
                                         fminf(fminf(u4.x,u5.x), fminf(u6.x,u7.x))));
                        float v1 = fminf(fB1.x,
                                   fminf(fminf(fminf(u0.y,u1.y), fminf(u2.y,u3.y)),
                                         fminf(fminf(u4.y,u5.y), fminf(u6.y,u7.y))));
                        sd[cur^1][rr+1][cc+1] = v0;
                        sd[cur^1][rr+1][cc+2] = v1;
                    }
                    if (act_b){
                        unsigned long long D0 = *(const unsigned long long*)&sd[cur][rr+3][cc];
                        unsigned long long D1 = *(const unsigned long long*)&sd[cur][rr+3][cc+2];
                        float2 fD0 = upk2(D0), fD1 = upk2(D1);
                        unsigned long long mixD = pk2(fD0.y, fD1.x);

                        unsigned long long s0 = add2(B0,   cst2b[0]);
                        unsigned long long s1 = add2(mixB, cst2b[1]);
                        unsigned long long s2 = add2(B1,   cst2b[2]);
                        unsigned long long s3 = add2(C0,   cst2b[3]);
                        unsigned long long s4 = add2(C1,   cst2b[4]);
                        unsigned long long s5 = add2(D0,   cst2b[5]);
                        unsigned long long s6 = add2(mixD, cst2b[6]);
                        unsigned long long s7 = add2(D1,   cst2b[7]);
                        float2 u0=upk2(s0),u1=upk2(s1),u2=upk2(s2),u3=upk2(s3);
                        float2 u4=upk2(s4),u5=upk2(s5),u6=upk2(s6),u7=upk2(s7);
                        float v0 = fminf(fC0.y,
                                   fminf(fminf(fminf(u0.x,u1.x), fminf(u2.x,u3.x)),
                                         fminf(fminf(u4.x,u5.x), fminf(u6.x,u7.x))));
                        float v1 = fminf(fC1.x,
                                   fminf(fminf(fminf(u0.y,u1.y), fminf(u2.y,u3.y)),
                                         fminf(fminf(u4.y,u5.y), fminf(u6.y,u7.y))));
                        sd[cur^1][rr+2][cc+1] = v0;
                        sd[cur^1][rr+2][cc+2] = v1;
                    }
                }
                __syncthreads();
            }

            if (p < 15){
                if (is_store){
                    __stcg(dst + (gh_s  )*WW + gw_s,     sd[0][rr+1][cc+1]);
                    __stcg(dst + (gh_s  )*WW + gw_s + 1, sd[0][rr+1][cc+2]);
                    __stcg(dst + (gh_s+1)*WW + gw_s,     sd[0][rr+2][cc+1]);
                    __stcg(dst + (gh_s+1)*WW + gw_s + 1, sd[0][rr+2][cc+2]);
                }
                __threadfence();
            } else {
                if (is_store){
                    int e = endn[0]*WW + endn[1];
                    float varEnd = g_var[e];
                    float q0 = softplusf(*dl), q1 = softplusf(*gm), q2 = softplusf(*bt);
                    #pragma unroll
                    for (int a=0; a<2; a++)
                        #pragma unroll
                        for (int b=0; b<2; b++){
                            int px = (gh_s+a)*WW + gw_s + b;
                            float om = g_omega[px];
                            float hv = q0*g_geo[px]
                                     + om*q1*(varEnd - g_var[px])
                                     + (1.0f - om)*q2*sqrtf(g_abs2[px]);
                            out[(size_t)px*10 + 0] = fmaxf(hv, 0.0f);
                            out[(size_t)px*10 + 9] = fminf(sd[0][rr+1+a][cc+1+b], BIGF);
                        }
                }
            }
        }

        if (p < 15){
            __syncthreads();
            if (tid == 0){
                atomicAdd(&g_arrive, 1u);
                unsigned target = NBLK * (unsigned)(p + 1);
                while (*((volatile unsigned*)&g_arrive) < target) __nanosleep(64);
            }
            __syncthreads();
        }
    }
}

// ---------------- launch ----------------
extern "C" void kernel_launch(void* const* d_in, const int* in_sizes, int n_in,
                              void* d_out, int out_size){
    const float* f = (const float*)d_in[0];
    float* out = (float*)d_out;

    static int smem_set = 0;
    if (!smem_set){
        cudaFuncSetAttribute(hc_k, cudaFuncAttributeMaxDynamicSharedMemorySize, 64592);
        smem_set = 1;
    }

    hc_k<<<dim3(16,16), 256, 64592>>>(f, out, (const float*)d_in[4], (const float*)d_in[5],
                                      (const float*)d_in[6], (const float*)d_in[7],
                                      (const int*)d_in[9]);
    dist_relax_persist<<<dim3(8,16), 768>>>((const int*)d_in[8], (const int*)d_in[9],
                                            (const float*)d_in[1], (const float*)d_in[2],
                                            (const float*)d_in[3], out);
}